// round 3
// baseline (speedup 1.0000x reference)
#include <cuda_runtime.h>
#include <math.h>

#define K_CTX 64
#define D_DIM 128
#define C_CAND 256
#define DS 200
#define EPS 1e-8f

// Scratch (device globals; no allocation allowed)
__device__ __align__(16) float g_A[K_CTX * D_DIM];
__device__ __align__(16) float g_AM[K_CTX * D_DIM];

// ---------------------------------------------------------------------------
// Kernel 1: gather A = table[t1_ctx] and compute AM = A @ att_mat
// ---------------------------------------------------------------------------
__global__ void prep_kernel(const float* __restrict__ table,
                            const float* __restrict__ att_mat,
                            const int* __restrict__ t1_ctx) {
    int k = blockIdx.x;
    int d = threadIdx.x;
    __shared__ float arow[D_DIM];

    long long r = (long long)t1_ctx[k];
    float a = table[r * D_DIM + d];
    arow[d] = a;
    g_A[k * D_DIM + d] = a;
    __syncthreads();

    float acc = 0.f;
#pragma unroll 8
    for (int e = 0; e < D_DIM; e++)
        acc = fmaf(arow[e], att_mat[e * D_DIM + d], acc);
    g_AM[k * D_DIM + d] = acc;
}

// ---------------------------------------------------------------------------
// Kernel 2: per-candidate fused pipeline. grid=256, block=512.
// Each warp w owns k-rows 4w..4w+3; each lane owns m-cols 2l, 2l+1.
// ---------------------------------------------------------------------------
#define SB_STRIDE 129
#define SMEM_FLOATS (8192 + 64*SB_STRIDE + 4*64 + 2*128 + 4)

__global__ __launch_bounds__(512, 2)
void cand_kernel(const float* __restrict__ table,
                 const float* __restrict__ str_t1,
                 const float* __restrict__ str_t2s,
                 const float* __restrict__ W,     // W_bi[0]: [128,128]
                 const float* __restrict__ b_bi,
                 const int* __restrict__ t2_ctx,
                 float* __restrict__ out) {
    extern __shared__ float sm[];
    float* sAM    = sm;                       // 64*128
    float* sB     = sAM + K_CTX * D_DIM;      // 64*129
    float* rowsum = sB + K_CTX * SB_STRIDE;   // 64
    float* colsum = rowsum + K_CTX;           // 64
    float* rows_w = colsum + K_CTX;           // 64
    float* cols_w = rows_w + K_CTX;           // 64
    float* newA   = cols_w + K_CTX;           // 128
    float* newB   = newA + D_DIM;             // 128
    float* scal   = newB + D_DIM;             // 4

    const int c    = blockIdx.x;
    const int tid  = threadIdx.x;
    const int wid  = tid >> 5;                // 0..15
    const int lane = tid & 31;

    if (tid < K_CTX) colsum[tid] = 0.f;
    if (tid < 4) scal[tid] = 0.f;
    __syncthreads();

    // --- stage AM into smem (float4) ---
    {
        const float4* src = (const float4*)g_AM;
        float4* dst = (float4*)sAM;
#pragma unroll
        for (int i = tid; i < K_CTX * D_DIM / 4; i += 512)
            dst[i] = src[i];
    }

    // --- gather B rows (float4 LDG, scalar STS into padded smem) ---
    const int* ctx = t2_ctx + c * K_CTX;
#pragma unroll
    for (int i = tid; i < K_CTX * D_DIM / 4; i += 512) {
        int m = i >> 5;            // row
        int v = i & 31;            // vec4 index within row
        float4 b4 = __ldg((const float4*)(table + (long long)ctx[m] * D_DIM) + v);
        float* dst = sB + m * SB_STRIDE + v * 4;
        dst[0] = b4.x; dst[1] = b4.y; dst[2] = b4.z; dst[3] = b4.w;
    }

    // --- string-branch cosine partials (overlaps with gather latency) ---
    {
        float pd = 0.f, p1 = 0.f, p2 = 0.f;
        if (tid < DS) {
            float x1 = str_t1[tid];
            float x2 = str_t2s[c * DS + tid];
            pd = x1 * x2; p1 = x1 * x1; p2 = x2 * x2;
        }
#pragma unroll
        for (int off = 16; off; off >>= 1) {
            pd += __shfl_down_sync(0xffffffffu, pd, off);
            p1 += __shfl_down_sync(0xffffffffu, p1, off);
            p2 += __shfl_down_sync(0xffffffffu, p2, off);
        }
        if (lane == 0 && wid < 7) {  // DS=200 spans first 7 warps
            atomicAdd(&scal[0], pd);
            atomicAdd(&scal[1], p1);
            atomicAdd(&scal[2], p2);
        }
    }
    __syncthreads();

    // --- sim = tanh(AM @ B^T): 4x2 register tile, never materialized ---
    {
        const float* amp = sAM + wid * 4 * D_DIM;       // warp-uniform
        const float* bp  = sB + (lane * 2) * SB_STRIDE;

        float acc00 = 0, acc01 = 0;
        float acc10 = 0, acc11 = 0;
        float acc20 = 0, acc21 = 0;
        float acc30 = 0, acc31 = 0;

#pragma unroll 4
        for (int j = 0; j < D_DIM; j++) {
            float a0 = amp[j];
            float a1 = amp[D_DIM + j];
            float a2 = amp[2 * D_DIM + j];
            float a3 = amp[3 * D_DIM + j];
            float b0 = bp[j];
            float b1 = bp[SB_STRIDE + j];
            acc00 = fmaf(a0, b0, acc00); acc01 = fmaf(a0, b1, acc01);
            acc10 = fmaf(a1, b0, acc10); acc11 = fmaf(a1, b1, acc11);
            acc20 = fmaf(a2, b0, acc20); acc21 = fmaf(a2, b1, acc21);
            acc30 = fmaf(a3, b0, acc30); acc31 = fmaf(a3, b1, acc31);
        }

        float s00 = tanhf(acc00), s01 = tanhf(acc01);
        float s10 = tanhf(acc10), s11 = tanhf(acc11);
        float s20 = tanhf(acc20), s21 = tanhf(acc21);
        float s30 = tanhf(acc30), s31 = tanhf(acc31);

        // rowsum: warp covers all 64 m-cols -> pure shfl reduction, no atomics
        float r0 = s00 + s01;
        float r1 = s10 + s11;
        float r2 = s20 + s21;
        float r3 = s30 + s31;
#pragma unroll
        for (int off = 16; off; off >>= 1) {
            r0 += __shfl_xor_sync(0xffffffffu, r0, off);
            r1 += __shfl_xor_sync(0xffffffffu, r1, off);
            r2 += __shfl_xor_sync(0xffffffffu, r2, off);
            r3 += __shfl_xor_sync(0xffffffffu, r3, off);
        }
        if (lane == 0) {
            rowsum[wid * 4 + 0] = r0;
            rowsum[wid * 4 + 1] = r1;
            rowsum[wid * 4 + 2] = r2;
            rowsum[wid * 4 + 3] = r3;
        }

        // colsum: partial over this warp's 4 k-rows -> shared atomics
        atomicAdd(&colsum[lane * 2 + 0], s00 + s10 + s20 + s30);
        atomicAdd(&colsum[lane * 2 + 1], s01 + s11 + s21 + s31);
    }
    __syncthreads();

    // --- softmax over 64 values: warp 0 -> rows, warp 1 -> cols ---
    if (tid < 64) {
        const float* src = (tid < 32) ? rowsum : colsum;
        float* dst       = (tid < 32) ? rows_w : cols_w;
        int l = tid & 31;
        float v0 = src[l]      * (1.f / 64.f);
        float v1 = src[l + 32] * (1.f / 64.f);
        float mx = fmaxf(v0, v1);
#pragma unroll
        for (int off = 16; off; off >>= 1)
            mx = fmaxf(mx, __shfl_xor_sync(0xffffffffu, mx, off));
        float e0 = __expf(v0 - mx);
        float e1 = __expf(v1 - mx);
        float s = e0 + e1;
#pragma unroll
        for (int off = 16; off; off >>= 1)
            s += __shfl_xor_sync(0xffffffffu, s, off);
        float inv = 1.f / s;
        dst[l]      = e0 * inv;
        dst[l + 32] = e1 * inv;
    }
    __syncthreads();

    // --- new_A = rows @ A (gmem, L2-hot), new_B = cols @ B (smem) ---
    if (tid < D_DIM) {
        float na = 0.f, nb = 0.f;
#pragma unroll 8
        for (int k = 0; k < K_CTX; k++) {
            na = fmaf(rows_w[k], g_A[k * D_DIM + tid], na);
            nb = fmaf(cols_w[k], sB[k * SB_STRIDE + tid], nb);
        }
        newA[tid] = na;
        newB[tid] = nb;
    }
    __syncthreads();

    // --- con = newA @ W @ newB + b ---
    if (tid < D_DIM) {
        float s1 = 0.f;
#pragma unroll 8
        for (int d = 0; d < D_DIM; d++)
            s1 = fmaf(newA[d], W[d * D_DIM + tid], s1);
        float pc = s1 * newB[tid];
#pragma unroll
        for (int off = 16; off; off >>= 1)
            pc += __shfl_down_sync(0xffffffffu, pc, off);
        if (lane == 0) atomicAdd(&scal[3], pc);
    }
    __syncthreads();

    if (tid == 0) {
        float n1 = fmaxf(sqrtf(scal[1]), EPS);
        float n2 = fmaxf(sqrtf(scal[2]), EPS);
        float str_score = scal[0] / (n1 * n2);
        float con_score = scal[3] + b_bi[0];
        out[c] = 0.5f * str_score + 0.5f * con_score;
    }
}

// ---------------------------------------------------------------------------
extern "C" void kernel_launch(void* const* d_in, const int* in_sizes, int n_in,
                              void* d_out, int out_size) {
    const float* table   = (const float*)d_in[0];
    const float* str_t1  = (const float*)d_in[1];
    const float* str_t2s = (const float*)d_in[2];
    const float* att_mat = (const float*)d_in[3];
    const float* W_bi    = (const float*)d_in[4];
    const float* b_bi    = (const float*)d_in[5];
    const int*   t1_ctx  = (const int*)d_in[6];
    const int*   t2_ctx  = (const int*)d_in[7];
    float* out = (float*)d_out;

    cudaFuncSetAttribute(cand_kernel,
                         cudaFuncAttributeMaxDynamicSharedMemorySize,
                         SMEM_FLOATS * sizeof(float));

    prep_kernel<<<K_CTX, D_DIM>>>(table, att_mat, t1_ctx);
    cand_kernel<<<C_CAND, 512, SMEM_FLOATS * sizeof(float)>>>(
        table, str_t1, str_t2s, W_bi, b_bi, t2_ctx, out);
}

// round 4
// speedup vs baseline: 1.1621x; 1.1621x over previous
#include <cuda_runtime.h>
#include <math.h>

#define K_CTX 64
#define D_DIM 128
#define C_CAND 256
#define DS 200
#define EPS 1e-8f

// Scratch + sync (device globals; no allocation allowed)
__device__ __align__(16) float g_A[K_CTX * D_DIM];
__device__ __align__(16) float g_AM[K_CTX * D_DIM];
__device__ int g_count = 0;   // AM rows produced
__device__ int g_done  = 0;   // blocks finished (for reset)

// sB row stride: 140 floats = 560B (16B aligned rows; conflict-free LDS.128:
// vec4-group start banks 12*l mod 32 are pairwise disjoint per 8-lane phase)
#define SB_STRIDE 140
#define SB_VEC    (SB_STRIDE / 4)   // 35 float4 per row
#define SMEM_FLOATS (K_CTX * SB_STRIDE + 4 * 64 + 2 * 128 + 4)

// ---------------------------------------------------------------------------
// Single fused kernel. grid = 256 (one block per candidate), block = 512.
// Blocks 0..63 additionally produce one AM row (overlapped with gathers).
// ---------------------------------------------------------------------------
__global__ __launch_bounds__(512, 3)
void cand_kernel(const float* __restrict__ table,
                 const float* __restrict__ str_t1,
                 const float* __restrict__ str_t2s,
                 const float* __restrict__ att_mat,
                 const float* __restrict__ W,     // W_bi[0]: [128,128]
                 const float* __restrict__ b_bi,
                 const int* __restrict__ t1_ctx,
                 const int* __restrict__ t2_ctx,
                 float* __restrict__ out) {
    extern __shared__ __align__(16) float sm[];
    float* sB     = sm;                        // 64*140
    float* rowsum = sB + K_CTX * SB_STRIDE;    // 64
    float* colsum = rowsum + K_CTX;            // 64
    float* rows_w = colsum + K_CTX;            // 64
    float* cols_w = rows_w + K_CTX;            // 64
    float* newA   = cols_w + K_CTX;            // 128 (also producer arow scratch)
    float* newB   = newA + D_DIM;              // 128
    float* scal   = newB + D_DIM;              // 4

    const int c    = blockIdx.x;
    const int tid  = threadIdx.x;
    const int wid  = tid >> 5;                 // 0..15
    const int lane = tid & 31;

    // --- phase 1: zero accumulators (sync before any atomics touch them) ---
    if (tid < K_CTX) colsum[tid] = 0.f;
    if (tid < 4) scal[tid] = 0.f;
    __syncthreads();

    // --- phase 2: producer — blocks 0..63 compute AM row c ---
    if (c < K_CTX) {
        if (tid < D_DIM) {
            float a = table[(long long)t1_ctx[c] * D_DIM + tid];
            newA[tid] = a;                     // scratch use (free until later)
            g_A[c * D_DIM + tid] = a;
        }
        __syncthreads();
        if (tid < D_DIM) {
            float acc = 0.f;
#pragma unroll 8
            for (int e = 0; e < D_DIM; e++)
                acc = fmaf(newA[e], att_mat[e * D_DIM + tid], acc);
            g_AM[c * D_DIM + tid] = acc;
        }
        __syncthreads();
        if (tid == 0) {
            __threadfence();
            atomicAdd(&g_count, 1);
        }
    }

    // --- phase 3: gather B rows (float4 LDG + STS.128, random table rows) ---
    const int* ctx = t2_ctx + c * K_CTX;
    {
        float4* sB4 = (float4*)sB;
#pragma unroll
        for (int i = tid; i < K_CTX * (D_DIM / 4); i += 512) {
            int m = i >> 5;                    // row 0..63
            int v = i & 31;                    // vec4 idx 0..31
            float4 b4 = __ldg((const float4*)(table + (long long)ctx[m] * D_DIM) + v);
            sB4[m * SB_VEC + v] = b4;
        }
    }

    // --- phase 4: string-branch cosine partials (hides gather latency) ---
    {
        float pd = 0.f, p1 = 0.f, p2 = 0.f;
        if (tid < DS) {
            float x1 = str_t1[tid];
            float x2 = str_t2s[c * DS + tid];
            pd = x1 * x2; p1 = x1 * x1; p2 = x2 * x2;
        }
#pragma unroll
        for (int off = 16; off; off >>= 1) {
            pd += __shfl_down_sync(0xffffffffu, pd, off);
            p1 += __shfl_down_sync(0xffffffffu, p1, off);
            p2 += __shfl_down_sync(0xffffffffu, p2, off);
        }
        if (lane == 0 && wid < 7) {
            atomicAdd(&scal[0], pd);
            atomicAdd(&scal[1], p1);
            atomicAdd(&scal[2], p2);
        }
    }

    // --- phase 5: wait for all 64 AM rows, then block-wide barrier ---
    if (tid == 0) {
        while (((volatile int*)&g_count)[0] < K_CTX) {}
        __threadfence();
    }
    __syncthreads();   // also orders gather STS + colsum zeros before sim

    // --- phase 6: sim = tanh(AM @ B^T), 4 k-rows x 2 m-cols per thread ---
    {
        const float4* am0 = (const float4*)(g_AM + (wid * 4 + 0) * D_DIM);
        const float4* am1 = (const float4*)(g_AM + (wid * 4 + 1) * D_DIM);
        const float4* am2 = (const float4*)(g_AM + (wid * 4 + 2) * D_DIM);
        const float4* am3 = (const float4*)(g_AM + (wid * 4 + 3) * D_DIM);
        const float4* b0p = (const float4*)(sB + lane * SB_STRIDE);
        const float4* b1p = (const float4*)(sB + (lane + 32) * SB_STRIDE);

        float acc00 = 0, acc01 = 0;
        float acc10 = 0, acc11 = 0;
        float acc20 = 0, acc21 = 0;
        float acc30 = 0, acc31 = 0;

#pragma unroll 4
        for (int jv = 0; jv < D_DIM / 4; jv++) {
            float4 a0 = am0[jv];
            float4 a1 = am1[jv];
            float4 a2 = am2[jv];
            float4 a3 = am3[jv];
            float4 b0 = b0p[jv];
            float4 b1 = b1p[jv];

            acc00 = fmaf(a0.x, b0.x, acc00); acc00 = fmaf(a0.y, b0.y, acc00);
            acc00 = fmaf(a0.z, b0.z, acc00); acc00 = fmaf(a0.w, b0.w, acc00);
            acc01 = fmaf(a0.x, b1.x, acc01); acc01 = fmaf(a0.y, b1.y, acc01);
            acc01 = fmaf(a0.z, b1.z, acc01); acc01 = fmaf(a0.w, b1.w, acc01);

            acc10 = fmaf(a1.x, b0.x, acc10); acc10 = fmaf(a1.y, b0.y, acc10);
            acc10 = fmaf(a1.z, b0.z, acc10); acc10 = fmaf(a1.w, b0.w, acc10);
            acc11 = fmaf(a1.x, b1.x, acc11); acc11 = fmaf(a1.y, b1.y, acc11);
            acc11 = fmaf(a1.z, b1.z, acc11); acc11 = fmaf(a1.w, b1.w, acc11);

            acc20 = fmaf(a2.x, b0.x, acc20); acc20 = fmaf(a2.y, b0.y, acc20);
            acc20 = fmaf(a2.z, b0.z, acc20); acc20 = fmaf(a2.w, b0.w, acc20);
            acc21 = fmaf(a2.x, b1.x, acc21); acc21 = fmaf(a2.y, b1.y, acc21);
            acc21 = fmaf(a2.z, b1.z, acc21); acc21 = fmaf(a2.w, b1.w, acc21);

            acc30 = fmaf(a3.x, b0.x, acc30); acc30 = fmaf(a3.y, b0.y, acc30);
            acc30 = fmaf(a3.z, b0.z, acc30); acc30 = fmaf(a3.w, b0.w, acc30);
            acc31 = fmaf(a3.x, b1.x, acc31); acc31 = fmaf(a3.y, b1.y, acc31);
            acc31 = fmaf(a3.z, b1.z, acc31); acc31 = fmaf(a3.w, b1.w, acc31);
        }

        float s00 = tanhf(acc00), s01 = tanhf(acc01);
        float s10 = tanhf(acc10), s11 = tanhf(acc11);
        float s20 = tanhf(acc20), s21 = tanhf(acc21);
        float s30 = tanhf(acc30), s31 = tanhf(acc31);

        // rowsum: warp spans all 64 m-cols -> pure shfl reduction
        float r0 = s00 + s01;
        float r1 = s10 + s11;
        float r2 = s20 + s21;
        float r3 = s30 + s31;
#pragma unroll
        for (int off = 16; off; off >>= 1) {
            r0 += __shfl_xor_sync(0xffffffffu, r0, off);
            r1 += __shfl_xor_sync(0xffffffffu, r1, off);
            r2 += __shfl_xor_sync(0xffffffffu, r2, off);
            r3 += __shfl_xor_sync(0xffffffffu, r3, off);
        }
        if (lane == 0) {
            rowsum[wid * 4 + 0] = r0;
            rowsum[wid * 4 + 1] = r1;
            rowsum[wid * 4 + 2] = r2;
            rowsum[wid * 4 + 3] = r3;
        }

        // colsum: partial over this warp's 4 k-rows (bank-conflict-free)
        atomicAdd(&colsum[lane],      s00 + s10 + s20 + s30);
        atomicAdd(&colsum[lane + 32], s01 + s11 + s21 + s31);
    }
    __syncthreads();

    // --- phase 7: softmax over 64: warp 0 -> rows, warp 1 -> cols ---
    if (tid < 64) {
        const float* src = (tid < 32) ? rowsum : colsum;
        float* dst       = (tid < 32) ? rows_w : cols_w;
        int l = tid & 31;
        float v0 = src[l]      * (1.f / 64.f);
        float v1 = src[l + 32] * (1.f / 64.f);
        float mx = fmaxf(v0, v1);
#pragma unroll
        for (int off = 16; off; off >>= 1)
            mx = fmaxf(mx, __shfl_xor_sync(0xffffffffu, mx, off));
        float e0 = __expf(v0 - mx);
        float e1 = __expf(v1 - mx);
        float s = e0 + e1;
#pragma unroll
        for (int off = 16; off; off >>= 1)
            s += __shfl_xor_sync(0xffffffffu, s, off);
        float inv = 1.f / s;
        dst[l]      = e0 * inv;
        dst[l + 32] = e1 * inv;
    }
    __syncthreads();

    // --- phase 8: new_A = rows @ A (L2-hot gmem), new_B = cols @ B (smem) ---
    if (tid < D_DIM) {
        float na = 0.f, nb = 0.f;
#pragma unroll 8
        for (int k = 0; k < K_CTX; k++) {
            na = fmaf(rows_w[k], g_A[k * D_DIM + tid], na);
            nb = fmaf(cols_w[k], sB[k * SB_STRIDE + tid], nb);
        }
        newA[tid] = na;
        newB[tid] = nb;
    }
    __syncthreads();

    // --- phase 9: con = newA @ W @ newB + b ---
    if (tid < D_DIM) {
        float s1 = 0.f;
#pragma unroll 8
        for (int d = 0; d < D_DIM; d++)
            s1 = fmaf(newA[d], W[d * D_DIM + tid], s1);
        float pc = s1 * newB[tid];
#pragma unroll
        for (int off = 16; off; off >>= 1)
            pc += __shfl_down_sync(0xffffffffu, pc, off);
        if (lane == 0) atomicAdd(&scal[3], pc);
    }
    __syncthreads();

    if (tid == 0) {
        float n1 = fmaxf(sqrtf(scal[1]), EPS);
        float n2 = fmaxf(sqrtf(scal[2]), EPS);
        float str_score = scal[0] / (n1 * n2);
        float con_score = scal[3] + b_bi[0];
        out[c] = 0.5f * str_score + 0.5f * con_score;

        // reset counters for next (graph-replayed) launch: last block cleans up
        int d = atomicAdd(&g_done, 1);
        if (d == C_CAND - 1) {
            g_done  = 0;
            g_count = 0;
        }
    }
}

// ---------------------------------------------------------------------------
extern "C" void kernel_launch(void* const* d_in, const int* in_sizes, int n_in,
                              void* d_out, int out_size) {
    const float* table   = (const float*)d_in[0];
    const float* str_t1  = (const float*)d_in[1];
    const float* str_t2s = (const float*)d_in[2];
    const float* att_mat = (const float*)d_in[3];
    const float* W_bi    = (const float*)d_in[4];
    const float* b_bi    = (const float*)d_in[5];
    const int*   t1_ctx  = (const int*)d_in[6];
    const int*   t2_ctx  = (const int*)d_in[7];
    float* out = (float*)d_out;

    cand_kernel<<<C_CAND, 512, SMEM_FLOATS * sizeof(float)>>>(
        table, str_t1, str_t2s, att_mat, W_bi, b_bi, t1_ctx, t2_ctx, out);
}

// round 5
// speedup vs baseline: 1.3550x; 1.1660x over previous
#include <cuda_runtime.h>
#include <math.h>

#define K_CTX 64
#define D_DIM 128
#define C_CAND 256
#define DS 200
#define EPS 1e-8f

// Scratch + sync (device globals; no allocation allowed)
__device__ __align__(16) float g_A[K_CTX * D_DIM];
__device__ __align__(16) float g_AM[K_CTX * D_DIM];
__device__ int g_count = 0;   // AM rows produced
__device__ int g_done  = 0;   // blocks finished (for reset)

// sB row stride: 140 floats (16B-aligned rows; LDS.128 conflict-free:
// per 8-lane phase, vec4 start banks {0,12,24,4,16,28,8,20} cover all 32 banks)
#define SB_STRIDE 140
#define SB_VEC    (SB_STRIDE / 4)   // 35 float4 per row
#define SMEM_FLOATS (K_CTX * D_DIM + K_CTX * SB_STRIDE + 4 * 64 + 2 * 128 + 4)

// ---------------------------------------------------------------------------
// Single fused kernel. grid = 256 (one block per candidate), block = 512.
// Blocks 0..63 additionally produce one AM row (all 512 threads cooperate).
// ---------------------------------------------------------------------------
__global__ __launch_bounds__(512, 3)
void cand_kernel(const float* __restrict__ table,
                 const float* __restrict__ str_t1,
                 const float* __restrict__ str_t2s,
                 const float* __restrict__ att_mat,
                 const float* __restrict__ W,     // W_bi[0]: [128,128]
                 const float* __restrict__ b_bi,
                 const int* __restrict__ t1_ctx,
                 const int* __restrict__ t2_ctx,
                 float* __restrict__ out) {
    extern __shared__ __align__(16) float sm[];
    float* sAM    = sm;                        // 64*128 (also producer scratch)
    float* sB     = sAM + K_CTX * D_DIM;       // 64*140
    float* rowsum = sB + K_CTX * SB_STRIDE;    // 64
    float* colsum = rowsum + K_CTX;            // 64
    float* rows_w = colsum + K_CTX;            // 64
    float* cols_w = rows_w + K_CTX;            // 64
    float* newA   = cols_w + K_CTX;            // 128 (also producer arow)
    float* newB   = newA + D_DIM;              // 128
    float* scal   = newB + D_DIM;              // 4

    const int c    = blockIdx.x;
    const int tid  = threadIdx.x;
    const int wid  = tid >> 5;                 // 0..15
    const int lane = tid & 31;

    // --- phase 1: zero accumulators ---
    if (tid < K_CTX) colsum[tid] = 0.f;
    if (tid < 4) scal[tid] = 0.f;

    // --- phase 2: producer — blocks 0..63 compute AM row c (512 threads) ---
    if (c < K_CTX) {
        if (tid < D_DIM) {
            float a = table[(long long)t1_ctx[c] * D_DIM + tid];
            newA[tid] = a;
            g_A[c * D_DIM + tid] = a;
        }
        __syncthreads();
        {
            // thread (q,d): partial over e in [32q, 32q+32)
            const int d = tid & 127;
            const int q = tid >> 7;
            const float* att = att_mat + (q * 32) * D_DIM + d;
            const float* ar  = newA + q * 32;
            float acc = 0.f;
#pragma unroll
            for (int e = 0; e < 32; e++)
                acc = fmaf(ar[e], att[e * D_DIM], acc);
            sAM[tid] = acc;   // scratch [4][128]
        }
        __syncthreads();
        if (tid < D_DIM) {
            float v = sAM[tid] + sAM[D_DIM + tid] + sAM[2 * D_DIM + tid]
                    + sAM[3 * D_DIM + tid];
            g_AM[c * D_DIM + tid] = v;
            __threadfence();   // make row visible before flag
        }
        __syncthreads();
        if (tid == 0) atomicAdd(&g_count, 1);
    } else {
        __syncthreads();   // match barrier count not needed cross-block; orders zeros
    }

    // --- phase 3: gather B rows (float4 LDG + STS.128, random table rows) ---
    const int* ctx = t2_ctx + c * K_CTX;
    {
        float4* sB4 = (float4*)sB;
#pragma unroll
        for (int i = tid; i < K_CTX * (D_DIM / 4); i += 512) {
            int m = i >> 5;                    // row 0..63
            int v = i & 31;                    // vec4 idx 0..31
            float4 b4 = __ldg((const float4*)(table + (long long)ctx[m] * D_DIM) + v);
            sB4[m * SB_VEC + v] = b4;
        }
    }

    // --- phase 4: string-branch cosine partials (hides gather latency) ---
    {
        float pd = 0.f, p1 = 0.f, p2 = 0.f;
        if (tid < DS) {
            float x1 = str_t1[tid];
            float x2 = str_t2s[c * DS + tid];
            pd = x1 * x2; p1 = x1 * x1; p2 = x2 * x2;
        }
#pragma unroll
        for (int off = 16; off; off >>= 1) {
            pd += __shfl_down_sync(0xffffffffu, pd, off);
            p1 += __shfl_down_sync(0xffffffffu, p1, off);
            p2 += __shfl_down_sync(0xffffffffu, p2, off);
        }
        if (lane == 0 && wid < 7) {
            atomicAdd(&scal[0], pd);
            atomicAdd(&scal[1], p1);
            atomicAdd(&scal[2], p2);
        }
    }

    // --- phase 5: wait for all 64 AM rows ---
    if (tid == 0) {
        while (((volatile int*)&g_count)[0] < K_CTX) {}
        __threadfence();
    }
    __syncthreads();

    // --- phase 5b: stage AM into smem (L2-hot, 32 KB; kills per-iter LDG) ---
    {
        const float4* src = (const float4*)g_AM;
        float4* dst = (float4*)sAM;
#pragma unroll
        for (int i = tid; i < K_CTX * D_DIM / 4; i += 512)
            dst[i] = src[i];
    }
    __syncthreads();

    // --- phase 6: sim = tanh(AM @ B^T), 4 k-rows x 2 m-cols per thread ---
    {
        const float4* am0 = (const float4*)(sAM + (wid * 4 + 0) * D_DIM);
        const float4* am1 = (const float4*)(sAM + (wid * 4 + 1) * D_DIM);
        const float4* am2 = (const float4*)(sAM + (wid * 4 + 2) * D_DIM);
        const float4* am3 = (const float4*)(sAM + (wid * 4 + 3) * D_DIM);
        const float4* b0p = (const float4*)(sB + lane * SB_STRIDE);
        const float4* b1p = (const float4*)(sB + (lane + 32) * SB_STRIDE);

        float acc00 = 0, acc01 = 0;
        float acc10 = 0, acc11 = 0;
        float acc20 = 0, acc21 = 0;
        float acc30 = 0, acc31 = 0;

#pragma unroll 4
        for (int jv = 0; jv < D_DIM / 4; jv++) {
            float4 a0 = am0[jv];
            float4 a1 = am1[jv];
            float4 a2 = am2[jv];
            float4 a3 = am3[jv];
            float4 b0 = b0p[jv];
            float4 b1 = b1p[jv];

            acc00 = fmaf(a0.x, b0.x, acc00); acc00 = fmaf(a0.y, b0.y, acc00);
            acc00 = fmaf(a0.z, b0.z, acc00); acc00 = fmaf(a0.w, b0.w, acc00);
            acc01 = fmaf(a0.x, b1.x, acc01); acc01 = fmaf(a0.y, b1.y, acc01);
            acc01 = fmaf(a0.z, b1.z, acc01); acc01 = fmaf(a0.w, b1.w, acc01);

            acc10 = fmaf(a1.x, b0.x, acc10); acc10 = fmaf(a1.y, b0.y, acc10);
            acc10 = fmaf(a1.z, b0.z, acc10); acc10 = fmaf(a1.w, b0.w, acc10);
            acc11 = fmaf(a1.x, b1.x, acc11); acc11 = fmaf(a1.y, b1.y, acc11);
            acc11 = fmaf(a1.z, b1.z, acc11); acc11 = fmaf(a1.w, b1.w, acc11);

            acc20 = fmaf(a2.x, b0.x, acc20); acc20 = fmaf(a2.y, b0.y, acc20);
            acc20 = fmaf(a2.z, b0.z, acc20); acc20 = fmaf(a2.w, b0.w, acc20);
            acc21 = fmaf(a2.x, b1.x, acc21); acc21 = fmaf(a2.y, b1.y, acc21);
            acc21 = fmaf(a2.z, b1.z, acc21); acc21 = fmaf(a2.w, b1.w, acc21);

            acc30 = fmaf(a3.x, b0.x, acc30); acc30 = fmaf(a3.y, b0.y, acc30);
            acc30 = fmaf(a3.z, b0.z, acc30); acc30 = fmaf(a3.w, b0.w, acc30);
            acc31 = fmaf(a3.x, b1.x, acc31); acc31 = fmaf(a3.y, b1.y, acc31);
            acc31 = fmaf(a3.z, b1.z, acc31); acc31 = fmaf(a3.w, b1.w, acc31);
        }

        float s00 = tanhf(acc00), s01 = tanhf(acc01);
        float s10 = tanhf(acc10), s11 = tanhf(acc11);
        float s20 = tanhf(acc20), s21 = tanhf(acc21);
        float s30 = tanhf(acc30), s31 = tanhf(acc31);

        // rowsum: warp spans all 64 m-cols -> pure shfl reduction
        float r0 = s00 + s01;
        float r1 = s10 + s11;
        float r2 = s20 + s21;
        float r3 = s30 + s31;
#pragma unroll
        for (int off = 16; off; off >>= 1) {
            r0 += __shfl_xor_sync(0xffffffffu, r0, off);
            r1 += __shfl_xor_sync(0xffffffffu, r1, off);
            r2 += __shfl_xor_sync(0xffffffffu, r2, off);
            r3 += __shfl_xor_sync(0xffffffffu, r3, off);
        }
        if (lane == 0) {
            rowsum[wid * 4 + 0] = r0;
            rowsum[wid * 4 + 1] = r1;
            rowsum[wid * 4 + 2] = r2;
            rowsum[wid * 4 + 3] = r3;
        }

        // colsum: partial over this warp's 4 k-rows (distinct banks)
        atomicAdd(&colsum[lane],      s00 + s10 + s20 + s30);
        atomicAdd(&colsum[lane + 32], s01 + s11 + s21 + s31);
    }
    __syncthreads();

    // --- phase 7: softmax over 64: warp 0 -> rows, warp 1 -> cols ---
    if (tid < 64) {
        const float* src = (tid < 32) ? rowsum : colsum;
        float* dst       = (tid < 32) ? rows_w : cols_w;
        int l = tid & 31;
        float v0 = src[l]      * (1.f / 64.f);
        float v1 = src[l + 32] * (1.f / 64.f);
        float mx = fmaxf(v0, v1);
#pragma unroll
        for (int off = 16; off; off >>= 1)
            mx = fmaxf(mx, __shfl_xor_sync(0xffffffffu, mx, off));
        float e0 = __expf(v0 - mx);
        float e1 = __expf(v1 - mx);
        float s = e0 + e1;
#pragma unroll
        for (int off = 16; off; off >>= 1)
            s += __shfl_xor_sync(0xffffffffu, s, off);
        float inv = 1.f / s;
        dst[l]      = e0 * inv;
        dst[l + 32] = e1 * inv;
    }
    __syncthreads();

    // --- phase 8: new_A = rows @ A (L2-hot gmem), new_B = cols @ B (smem) ---
    if (tid < D_DIM) {
        float na = 0.f, nb = 0.f;
#pragma unroll 8
        for (int k = 0; k < K_CTX; k++) {
            na = fmaf(rows_w[k], __ldg(g_A + k * D_DIM + tid), na);
            nb = fmaf(cols_w[k], sB[k * SB_STRIDE + tid], nb);
        }
        newA[tid] = na;
        newB[tid] = nb;
    }
    __syncthreads();

    // --- phase 9: con = newA @ W @ newB + b ---
    if (tid < D_DIM) {
        float s1 = 0.f;
#pragma unroll 8
        for (int d = 0; d < D_DIM; d++)
            s1 = fmaf(newA[d], W[d * D_DIM + tid], s1);
        float pc = s1 * newB[tid];
#pragma unroll
        for (int off = 16; off; off >>= 1)
            pc += __shfl_down_sync(0xffffffffu, pc, off);
        if (lane == 0) atomicAdd(&scal[3], pc);
    }
    __syncthreads();

    if (tid == 0) {
        float n1 = fmaxf(sqrtf(scal[1]), EPS);
        float n2 = fmaxf(sqrtf(scal[2]), EPS);
        float str_score = scal[0] / (n1 * n2);
        float con_score = scal[3] + b_bi[0];
        out[c] = 0.5f * str_score + 0.5f * con_score;

        // reset counters for next (graph-replayed) launch
        int d = atomicAdd(&g_done, 1);
        if (d == C_CAND - 1) {
            g_done  = 0;
            g_count = 0;
        }
    }
}

// ---------------------------------------------------------------------------
extern "C" void kernel_launch(void* const* d_in, const int* in_sizes, int n_in,
                              void* d_out, int out_size) {
    const float* table   = (const float*)d_in[0];
    const float* str_t1  = (const float*)d_in[1];
    const float* str_t2s = (const float*)d_in[2];
    const float* att_mat = (const float*)d_in[3];
    const float* W_bi    = (const float*)d_in[4];
    const float* b_bi    = (const float*)d_in[5];
    const int*   t1_ctx  = (const int*)d_in[6];
    const int*   t2_ctx  = (const int*)d_in[7];
    float* out = (float*)d_out;

    cudaFuncSetAttribute(cand_kernel,
                         cudaFuncAttributeMaxDynamicSharedMemorySize,
                         SMEM_FLOATS * sizeof(float));

    cand_kernel<<<C_CAND, 512, SMEM_FLOATS * sizeof(float)>>>(
        table, str_t1, str_t2s, att_mat, W_bi, b_bi, t1_ctx, t2_ctx, out);
}